// round 1
// baseline (speedup 1.0000x reference)
#include <cuda_runtime.h>
#include <cuda_bf16.h>
#include <stdint.h>

// Problem constants
#define M_TOK   262144
#define K_DIM   64
#define N_DIM   64
#define N_EXP   8

#define TILE_M  128
#define NTHREADS 256
#define MAX_TILES (M_TOK / TILE_M + N_EXP)   // 2056

// ---------------- device scratch (no allocations allowed) ----------------
__device__ int g_counts[N_EXP];
__device__ int g_cursor[N_EXP];
__device__ int g_perm[M_TOK];
__device__ int g_tile_e[MAX_TILES];
__device__ int g_tile_base[MAX_TILES];
__device__ int g_tile_rows[MAX_TILES];
__device__ int g_ntiles;

// ---------------- K0: zero expert counters ----------------
__global__ void k_zero() {
    int t = threadIdx.x;
    if (t < N_EXP) g_counts[t] = 0;
}

// ---------------- K1: histogram of sel ----------------
__global__ void k_hist(const int* __restrict__ sel) {
    __shared__ int cnt[N_EXP];
    int tid = threadIdx.x;
    if (tid < N_EXP) cnt[tid] = 0;
    __syncthreads();
    for (int m = blockIdx.x * NTHREADS + tid; m < M_TOK; m += gridDim.x * NTHREADS) {
        atomicAdd(&cnt[sel[m]], 1);
    }
    __syncthreads();
    if (tid < N_EXP) atomicAdd(&g_counts[tid], cnt[tid]);
}

// ---------------- K2: scan + tile table (1 warp) ----------------
__global__ void k_scan() {
    __shared__ int off[N_EXP + 1];
    __shared__ int ts[N_EXP + 1];
    __shared__ int cnts[N_EXP];
    int lane = threadIdx.x;
    if (lane == 0) {
        int o = 0, t = 0;
        for (int e = 0; e < N_EXP; e++) {
            int c = g_counts[e];
            cnts[e] = c;
            off[e] = o;
            ts[e] = t;
            g_cursor[e] = o;
            o += c;
            t += (c + TILE_M - 1) >> 7;
        }
        off[N_EXP] = o;
        ts[N_EXP] = t;
        g_ntiles = t;
    }
    __syncwarp();
    int ntiles = ts[N_EXP];
    for (int t = lane; t < ntiles; t += 32) {
        int e = 0;
        while (ts[e + 1] <= t) e++;
        int j = t - ts[e];
        g_tile_e[t] = e;
        g_tile_base[t] = off[e] + j * TILE_M;
        int rem = cnts[e] - j * TILE_M;
        g_tile_rows[t] = rem < TILE_M ? rem : TILE_M;
    }
}

// ---------------- K3: scatter tokens into expert-grouped perm ----------------
// Block-local ranking in shared memory; one global atomic per (block, expert).
__global__ void k_scatter(const int* __restrict__ sel) {
    __shared__ int cnt[N_EXP];
    __shared__ int basesh[N_EXP];
    int tid = threadIdx.x;
    int b = blockIdx.x;
    if (tid < N_EXP) cnt[tid] = 0;
    __syncthreads();
    int myE[4], myR[4];
#pragma unroll
    for (int i = 0; i < 4; i++) {
        int m = b * 1024 + i * NTHREADS + tid;
        int e = sel[m];
        myE[i] = e;
        myR[i] = atomicAdd(&cnt[e], 1);
    }
    __syncthreads();
    if (tid < N_EXP) basesh[tid] = atomicAdd(&g_cursor[tid], cnt[tid]);
    __syncthreads();
#pragma unroll
    for (int i = 0; i < 4; i++) {
        int m = b * 1024 + i * NTHREADS + tid;
        g_perm[basesh[myE[i]] + myR[i]] = m;
    }
}

// ---------------- K4: grouped GEMM ----------------
// One block = one tile of up to 128 tokens (single expert) x 64 cols, K=64.
// smem: ws[64][64] (w[e], 16KB) + xst[64][128] (x^T tile, 32KB) = 48KB dynamic.
// Thread microtile: 8 tokens x 4 cols. tid = tn + 16*tr; tn in [0,16) cols,
// tr in [0,16) token groups. x loads broadcast across 16 lanes; w loads are
// 16 distinct float4 -> 2-phase, conflict-free.
__global__ void __launch_bounds__(NTHREADS) k_gemm(
    const float* __restrict__ x, const float* __restrict__ w,
    float* __restrict__ out)
{
    int t = blockIdx.x;
    if (t >= g_ntiles) return;
    int e    = g_tile_e[t];
    int base = g_tile_base[t];
    int rows = g_tile_rows[t];

    extern __shared__ float smem[];
    float* ws  = smem;           // 4096 floats
    float* xst = smem + 4096;    // 64*128 floats

    int tid = threadIdx.x;

    // Load w[e] (16KB), straight copy, coalesced.
    {
        const float4* w4 = (const float4*)(w + e * (K_DIM * N_DIM));
        float4* ws4 = (float4*)ws;
#pragma unroll
        for (int i = tid; i < 1024; i += NTHREADS) ws4[i] = w4[i];
    }

    // Gather x rows and transpose into xst[k][r].
    // i in [0, 2048): r = i & 127 (fast-varying -> conflict-free smem stores),
    // c4 = i >> 7 (float4 column).
    for (int i = tid; i < 2048; i += NTHREADS) {
        int r  = i & 127;
        int c4 = i >> 7;
        float4 v = make_float4(0.f, 0.f, 0.f, 0.f);
        if (r < rows) {
            int tok = g_perm[base + r];
            v = ((const float4*)x)[tok * 16 + c4];
        }
        int k0 = c4 * 4;
        xst[(k0 + 0) * TILE_M + r] = v.x;
        xst[(k0 + 1) * TILE_M + r] = v.y;
        xst[(k0 + 2) * TILE_M + r] = v.z;
        xst[(k0 + 3) * TILE_M + r] = v.w;
    }
    __syncthreads();

    int tn = tid & 15;   // col group: cols [tn*4, tn*4+4)
    int tr = tid >> 4;   // token group: rows [tr*8, tr*8+8)

    float acc[8][4];
#pragma unroll
    for (int i = 0; i < 8; i++)
#pragma unroll
        for (int j = 0; j < 4; j++) acc[i][j] = 0.f;

#pragma unroll 8
    for (int k = 0; k < K_DIM; k++) {
        float4 wv = ((const float4*)(ws + k * N_DIM))[tn];
        float4 xa = ((const float4*)(xst + k * TILE_M))[tr * 2];
        float4 xb = ((const float4*)(xst + k * TILE_M))[tr * 2 + 1];
        float xv[8] = {xa.x, xa.y, xa.z, xa.w, xb.x, xb.y, xb.z, xb.w};
#pragma unroll
        for (int i = 0; i < 8; i++) {
            acc[i][0] = fmaf(xv[i], wv.x, acc[i][0]);
            acc[i][1] = fmaf(xv[i], wv.y, acc[i][1]);
            acc[i][2] = fmaf(xv[i], wv.z, acc[i][2]);
            acc[i][3] = fmaf(xv[i], wv.w, acc[i][3]);
        }
    }

    // Scatter output rows (256B coalesced per token row across 16 lanes).
#pragma unroll
    for (int i = 0; i < 8; i++) {
        int r = tr * 8 + i;
        if (r < rows) {
            int tok = g_perm[base + r];
            ((float4*)out)[tok * 16 + tn] =
                make_float4(acc[i][0], acc[i][1], acc[i][2], acc[i][3]);
        }
    }
}

// ---------------- launch ----------------
extern "C" void kernel_launch(void* const* d_in, const int* in_sizes, int n_in,
                              void* d_out, int out_size) {
    const float* x   = (const float*)d_in[0];
    const int*   sel = (const int*)d_in[1];
    const float* w   = (const float*)d_in[2];
    float*       out = (float*)d_out;

    (void)in_sizes; (void)n_in; (void)out_size;

    const int smem_bytes = (4096 + 64 * TILE_M) * (int)sizeof(float); // 48KB
    cudaFuncSetAttribute(k_gemm, cudaFuncAttributeMaxDynamicSharedMemorySize,
                         smem_bytes);

    k_zero<<<1, 32>>>();
    k_hist<<<256, NTHREADS>>>(sel);
    k_scan<<<1, 32>>>();
    k_scatter<<<256, NTHREADS>>>(sel);
    k_gemm<<<MAX_TILES, NTHREADS, smem_bytes>>>(x, w, out);
}

// round 3
// speedup vs baseline: 1.0998x; 1.0998x over previous
#include <cuda_runtime.h>
#include <cuda_bf16.h>
#include <stdint.h>

// Problem constants
#define M_TOK   262144
#define K_DIM   64
#define N_DIM   64
#define N_EXP   8

#define TILE_M  128
#define NTHREADS 256
#define MAX_TILES (M_TOK / TILE_M + N_EXP)   // 2056

// smem layout (ushort units), pitch 72 bf16 per row (144B: 4r mod 32 bank rotation)
#define APITCH 72
#define A_ELEMS (128 * APITCH)          // 9216 ushort
#define B_ELEMS (64 * APITCH)           // 4608 ushort
// [Ah | Al | Bh | Bl]
#define SMEM_USHORTS (2 * A_ELEMS + 2 * B_ELEMS)
#define SMEM_BYTES (SMEM_USHORTS * 2)   // 55296

// ---------------- device scratch ----------------
__device__ int g_counts[N_EXP];
__device__ int g_cursor[N_EXP];
__device__ int g_perm[M_TOK];
__device__ int g_tile_e[MAX_TILES];
__device__ int g_tile_base[MAX_TILES];
__device__ int g_tile_rows[MAX_TILES];
__device__ int g_ntiles;

// ---------------- K0: zero expert counters ----------------
__global__ void k_zero() {
    int t = threadIdx.x;
    if (t < N_EXP) g_counts[t] = 0;
}

// ---------------- K1: histogram (ballot-aggregated) ----------------
__global__ void k_hist(const int* __restrict__ sel) {
    __shared__ int cnt[N_EXP];
    int tid = threadIdx.x;
    int lid = tid & 31;
    if (tid < N_EXP) cnt[tid] = 0;
    __syncthreads();
    for (int m = blockIdx.x * NTHREADS + tid; m < M_TOK; m += gridDim.x * NTHREADS) {
        int e = sel[m];
#pragma unroll
        for (int ee = 0; ee < N_EXP; ee++) {
            unsigned msk = __ballot_sync(0xffffffffu, e == ee);
            if (lid == 0 && msk) atomicAdd(&cnt[ee], __popc(msk));
        }
    }
    __syncthreads();
    if (tid < N_EXP) atomicAdd(&g_counts[tid], cnt[tid]);
}

// ---------------- K2: scan + tile table (1 warp) ----------------
__global__ void k_scan() {
    __shared__ int off[N_EXP + 1];
    __shared__ int ts[N_EXP + 1];
    __shared__ int cnts[N_EXP];
    int lane = threadIdx.x;
    if (lane == 0) {
        int o = 0, t = 0;
        for (int e = 0; e < N_EXP; e++) {
            int c = g_counts[e];
            cnts[e] = c;
            off[e] = o;
            ts[e] = t;
            g_cursor[e] = o;
            o += c;
            t += (c + TILE_M - 1) >> 7;
        }
        off[N_EXP] = o;
        ts[N_EXP] = t;
        g_ntiles = t;
    }
    __syncwarp();
    int ntiles = ts[N_EXP];
    for (int t = lane; t < ntiles; t += 32) {
        int e = 0;
        while (ts[e + 1] <= t) e++;
        int j = t - ts[e];
        g_tile_e[t] = e;
        g_tile_base[t] = off[e] + j * TILE_M;
        int rem = cnts[e] - j * TILE_M;
        g_tile_rows[t] = rem < TILE_M ? rem : TILE_M;
    }
}

// ---------------- K3: scatter (warp-aggregated ranking) ----------------
__global__ void k_scatter(const int* __restrict__ sel) {
    __shared__ int cnt[N_EXP];
    __shared__ int basesh[N_EXP];
    int tid = threadIdx.x;
    int b = blockIdx.x;
    int lid = tid & 31;
    if (tid < N_EXP) cnt[tid] = 0;
    __syncthreads();
    int myE[4], myR[4];
#pragma unroll
    for (int i = 0; i < 4; i++) {
        int m = b * 1024 + i * NTHREADS + tid;
        int e = sel[m];
        myE[i] = e;
        int r = 0;
#pragma unroll
        for (int ee = 0; ee < N_EXP; ee++) {
            unsigned msk = __ballot_sync(0xffffffffu, e == ee);
            if (e == ee) {
                int leader = __ffs(msk) - 1;
                int wb;
                if (lid == leader) wb = atomicAdd(&cnt[ee], __popc(msk));
                wb = __shfl_sync(msk, wb, leader);
                r = wb + __popc(msk & ((1u << lid) - 1u));
            }
        }
        myR[i] = r;
    }
    __syncthreads();
    if (tid < N_EXP) basesh[tid] = atomicAdd(&g_cursor[tid], cnt[tid]);
    __syncthreads();
#pragma unroll
    for (int i = 0; i < 4; i++) {
        g_perm[basesh[myE[i]] + myR[i]] = b * 1024 + i * NTHREADS + tid;
    }
}

// ---------------- helpers ----------------
__device__ __forceinline__ void f2bf_split(float f, unsigned short& h, unsigned short& l) {
    __nv_bfloat16 hb = __float2bfloat16(f);
    __nv_bfloat16 lb = __float2bfloat16(f - __bfloat162float(hb));
    h = __bfloat16_as_ushort(hb);
    l = __bfloat16_as_ushort(lb);
}

__device__ __forceinline__ void mma_bf16(float* c, const uint32_t* a, const uint32_t* b) {
    asm volatile(
        "mma.sync.aligned.m16n8k16.row.col.f32.bf16.bf16.f32 "
        "{%0,%1,%2,%3}, {%4,%5,%6,%7}, {%8,%9}, {%0,%1,%2,%3};"
        : "+f"(c[0]), "+f"(c[1]), "+f"(c[2]), "+f"(c[3])
        : "r"(a[0]), "r"(a[1]), "r"(a[2]), "r"(a[3]), "r"(b[0]), "r"(b[1]));
}

// ---------------- K4: grouped GEMM via mma.sync (3x bf16 split) ----------------
// Block = 256 threads = 8 warps; tile = 128 tokens x 64 cols, K=64.
// Warp grid 4(M) x 2(N): warp computes 32x32 output.
// A smem: [128][64] bf16 hi/lo (row-major K), pitch 72.
// B smem: [64n][64k] bf16 hi/lo (k contiguous = "col-major" B), pitch 72.
__global__ void __launch_bounds__(NTHREADS) k_gemm_mma(
    const float* __restrict__ x, const float* __restrict__ w,
    float* __restrict__ out)
{
    int t = blockIdx.x;
    if (t >= g_ntiles) return;
    int e    = g_tile_e[t];
    int base = g_tile_base[t];
    int rows = g_tile_rows[t];

    extern __shared__ unsigned short sh[];
    unsigned short* Ah = sh;
    unsigned short* Al = Ah + A_ELEMS;
    unsigned short* Bh = Al + A_ELEMS;
    unsigned short* Bl = Bh + B_ELEMS;

    int tid = threadIdx.x;
    int wid = tid >> 5;
    int lane = tid & 31;

    // ---- build A: gather x rows, split hi/lo ----
    {
        int r    = tid >> 1;           // 0..127
        int half = tid & 1;            // k-range [half*32, half*32+32)
        bool valid = r < rows;
        const float4* xr = nullptr;
        if (valid) xr = (const float4*)x + (size_t)g_perm[base + r] * 16 + half * 8;
        unsigned short* ah = Ah + r * APITCH + half * 32;
        unsigned short* al = Al + r * APITCH + half * 32;
#pragma unroll
        for (int i = 0; i < 8; i++) {
            float4 v = valid ? xr[i] : make_float4(0.f, 0.f, 0.f, 0.f);
            unsigned short h0, l0, h1, l1, h2, l2, h3, l3;
            f2bf_split(v.x, h0, l0);
            f2bf_split(v.y, h1, l1);
            f2bf_split(v.z, h2, l2);
            f2bf_split(v.w, h3, l3);
            ((uint32_t*)(ah + i * 4))[0] = (uint32_t)h0 | ((uint32_t)h1 << 16);
            ((uint32_t*)(ah + i * 4))[1] = (uint32_t)h2 | ((uint32_t)h3 << 16);
            ((uint32_t*)(al + i * 4))[0] = (uint32_t)l0 | ((uint32_t)l1 << 16);
            ((uint32_t*)(al + i * 4))[1] = (uint32_t)l2 | ((uint32_t)l3 << 16);
        }
    }

    // ---- build B: transpose w[e] (K x N, N contiguous) into [n][k] ----
    {
        int n  = tid & 63;
        int kh = tid >> 6;             // k-range [kh*16, kh*16+16)
        const float* we = w + (size_t)e * (K_DIM * N_DIM);
        unsigned short* bh = Bh + n * APITCH;
        unsigned short* bl = Bl + n * APITCH;
#pragma unroll
        for (int i = 0; i < 8; i++) {
            int k = kh * 16 + 2 * i;
            float f0 = we[(size_t)k * N_DIM + n];
            float f1 = we[(size_t)(k + 1) * N_DIM + n];
            unsigned short h0, l0, h1, l1;
            f2bf_split(f0, h0, l0);
            f2bf_split(f1, h1, l1);
            *(uint32_t*)(bh + k) = (uint32_t)h0 | ((uint32_t)h1 << 16);
            *(uint32_t*)(bl + k) = (uint32_t)l0 | ((uint32_t)l1 << 16);
        }
    }
    __syncthreads();

    // ---- mma mainloop ----
    int wm = wid & 3;                  // rows [wm*32, +32)
    int wn = wid >> 2;                 // cols [wn*32, +32)
    int lq = lane >> 2;                // 0..7
    int lr = lane & 3;                 // 0..3

    float acc[2][4][4];
#pragma unroll
    for (int mt = 0; mt < 2; mt++)
#pragma unroll
        for (int nt = 0; nt < 4; nt++)
#pragma unroll
            for (int i = 0; i < 4; i++) acc[mt][nt][i] = 0.f;

#pragma unroll
    for (int pass = 0; pass < 3; pass++) {
        const unsigned short* As = (pass == 2) ? Al : Ah;
        const unsigned short* Bs = (pass == 1) ? Bl : Bh;
#pragma unroll
        for (int kt = 0; kt < 4; kt++) {
            int c0 = kt * 16 + 2 * lr;
            uint32_t afrag[2][4];
#pragma unroll
            for (int mt = 0; mt < 2; mt++) {
                int r = wm * 32 + mt * 16 + lq;
                afrag[mt][0] = *(const uint32_t*)&As[r * APITCH + c0];
                afrag[mt][1] = *(const uint32_t*)&As[(r + 8) * APITCH + c0];
                afrag[mt][2] = *(const uint32_t*)&As[r * APITCH + c0 + 8];
                afrag[mt][3] = *(const uint32_t*)&As[(r + 8) * APITCH + c0 + 8];
            }
#pragma unroll
            for (int nt = 0; nt < 4; nt++) {
                int n = wn * 32 + nt * 8 + lq;
                uint32_t bfrag[2];
                bfrag[0] = *(const uint32_t*)&Bs[n * APITCH + c0];
                bfrag[1] = *(const uint32_t*)&Bs[n * APITCH + c0 + 8];
                mma_bf16(acc[0][nt], afrag[0], bfrag);
                mma_bf16(acc[1][nt], afrag[1], bfrag);
            }
        }
    }

    // ---- epilogue: scatter to out ----
#pragma unroll
    for (int mt = 0; mt < 2; mt++) {
#pragma unroll
        for (int half = 0; half < 2; half++) {
            int r = wm * 32 + mt * 16 + half * 8 + lq;
            if (r < rows) {
                int tok = g_perm[base + r];
                float* orow = out + (size_t)tok * 64 + wn * 32 + 2 * lr;
#pragma unroll
                for (int nt = 0; nt < 4; nt++) {
                    float2 v = make_float2(acc[mt][nt][half * 2],
                                           acc[mt][nt][half * 2 + 1]);
                    *(float2*)(orow + nt * 8) = v;
                }
            }
        }
    }
}

// ---------------- launch ----------------
extern "C" void kernel_launch(void* const* d_in, const int* in_sizes, int n_in,
                              void* d_out, int out_size) {
    const float* x   = (const float*)d_in[0];
    const int*   sel = (const int*)d_in[1];
    const float* w   = (const float*)d_in[2];
    float*       out = (float*)d_out;

    (void)in_sizes; (void)n_in; (void)out_size;

    cudaFuncSetAttribute(k_gemm_mma, cudaFuncAttributeMaxDynamicSharedMemorySize,
                         SMEM_BYTES);

    k_zero<<<1, 32>>>();
    k_hist<<<256, NTHREADS>>>(sel);
    k_scan<<<1, 32>>>();
    k_scatter<<<256, NTHREADS>>>(sel);
    k_gemm_mma<<<MAX_TILES, NTHREADS, SMEM_BYTES>>>(x, w, out);
}

// round 4
// speedup vs baseline: 1.1745x; 1.0679x over previous
#include <cuda_runtime.h>
#include <cuda_bf16.h>
#include <stdint.h>

// Problem constants
#define M_TOK   262144
#define K_DIM   64
#define N_DIM   64
#define N_EXP   8

#define TILE_M  128
#define NTHREADS 256
#define MAX_TILES (M_TOK / TILE_M + N_EXP)   // 2056

// smem layout (ushort units), pitch 72 bf16 per row (144B: 4r mod 32 bank rotation)
#define APITCH 72
#define A_ELEMS (128 * APITCH)          // 9216 ushort
#define B_ELEMS (64 * APITCH)           // 4608 ushort
// [Ah | Al | Bh | Bl]
#define SMEM_USHORTS (2 * A_ELEMS + 2 * B_ELEMS)
#define SMEM_BYTES (SMEM_USHORTS * 2)   // 55296

// ---------------- device scratch ----------------
__device__ int g_counts[N_EXP];
__device__ int g_cursor[N_EXP];
__device__ int g_perm[M_TOK];
__device__ int g_tile_e[MAX_TILES];
__device__ int g_tile_base[MAX_TILES];
__device__ int g_tile_rows[MAX_TILES];
__device__ int g_ntiles;
// prepped weights: per expert, [hi: 64n x 72k][lo: 64n x 72k] ushort (bf16)
__device__ unsigned short g_wb[N_EXP][2][64 * APITCH];

// ---------------- K0: zero expert counters ----------------
__global__ void k_zero() {
    int t = threadIdx.x;
    if (t < N_EXP) g_counts[t] = 0;
}

// ---------------- helpers ----------------
__device__ __forceinline__ void f2bf_split(float f, unsigned short& h, unsigned short& l) {
    __nv_bfloat16 hb = __float2bfloat16(f);
    __nv_bfloat16 lb = __float2bfloat16(f - __bfloat162float(hb));
    h = __bfloat16_as_ushort(hb);
    l = __bfloat16_as_ushort(lb);
}

// ---------------- K_wprep: convert+transpose w -> bf16 hi/lo (once) ----------------
// 8 blocks (one per expert), 256 threads. Output layout == gemm smem B layout.
__global__ void k_wprep(const float* __restrict__ w) {
    int e = blockIdx.x;
    int tid = threadIdx.x;
    int n  = tid & 63;
    int kh = tid >> 6;                   // k range [kh*16, kh*16+16)
    const float* we = w + (size_t)e * (K_DIM * N_DIM);
    unsigned short* dh = &g_wb[e][0][n * APITCH];
    unsigned short* dl = &g_wb[e][1][n * APITCH];
#pragma unroll
    for (int i = 0; i < 8; i++) {
        int k = kh * 16 + 2 * i;
        float f0 = we[(size_t)k * N_DIM + n];
        float f1 = we[(size_t)(k + 1) * N_DIM + n];
        unsigned short h0, l0, h1, l1;
        f2bf_split(f0, h0, l0);
        f2bf_split(f1, h1, l1);
        *(uint32_t*)(dh + k) = (uint32_t)h0 | ((uint32_t)h1 << 16);
        *(uint32_t*)(dl + k) = (uint32_t)l0 | ((uint32_t)l1 << 16);
    }
}

// ---------------- K1: histogram (packed register counters) ----------------
// 128 blocks x 256 threads, 8 tokens/thread (2x int4). No per-token atomics.
__global__ void k_hist(const int* __restrict__ sel) {
    __shared__ int cnt[N_EXP];
    int tid = threadIdx.x;
    int lid = tid & 31;
    if (tid < N_EXP) cnt[tid] = 0;
    __syncthreads();

    int tgl = blockIdx.x * NTHREADS + tid;   // global thread id
    const int4* s4 = (const int4*)sel;
    int4 a = s4[tgl * 2];
    int4 b = s4[tgl * 2 + 1];

    // two u64s: experts 0-3 in pk0 (16-bit slots), 4-7 in pk1
    unsigned long long pk0 = 0, pk1 = 0;
    int ev[8] = {a.x, a.y, a.z, a.w, b.x, b.y, b.z, b.w};
#pragma unroll
    for (int i = 0; i < 8; i++) {
        int e = ev[i];
        if (e < 4) pk0 += 1ull << (16 * e);
        else       pk1 += 1ull << (16 * (e - 4));
    }
#pragma unroll
    for (int o = 16; o > 0; o >>= 1) {
        pk0 += __shfl_down_sync(0xffffffffu, pk0, o);
        pk1 += __shfl_down_sync(0xffffffffu, pk1, o);
    }
    if (lid == 0) {
#pragma unroll
        for (int e = 0; e < 4; e++) {
            int c0 = (int)((pk0 >> (16 * e)) & 0xffff);
            int c1 = (int)((pk1 >> (16 * e)) & 0xffff);
            if (c0) atomicAdd(&cnt[e], c0);
            if (c1) atomicAdd(&cnt[e + 4], c1);
        }
    }
    __syncthreads();
    if (tid < N_EXP && cnt[tid]) atomicAdd(&g_counts[tid], cnt[tid]);
}

// ---------------- K2: scan + tile table (1 warp) ----------------
__global__ void k_scan() {
    __shared__ int off[N_EXP + 1];
    __shared__ int ts[N_EXP + 1];
    __shared__ int cnts[N_EXP];
    int lane = threadIdx.x;
    if (lane == 0) {
        int o = 0, t = 0;
        for (int e = 0; e < N_EXP; e++) {
            int c = g_counts[e];
            cnts[e] = c;
            off[e] = o;
            ts[e] = t;
            g_cursor[e] = o;
            o += c;
            t += (c + TILE_M - 1) >> 7;
        }
        off[N_EXP] = o;
        ts[N_EXP] = t;
        g_ntiles = t;
    }
    __syncwarp();
    int ntiles = ts[N_EXP];
    for (int t = lane; t < ntiles; t += 32) {
        int e = 0;
        while (ts[e + 1] <= t) e++;
        int j = t - ts[e];
        g_tile_e[t] = e;
        g_tile_base[t] = off[e] + j * TILE_M;
        int rem = cnts[e] - j * TILE_M;
        g_tile_rows[t] = rem < TILE_M ? rem : TILE_M;
    }
}

// ---------------- K3: scatter (match_any ranking) ----------------
// 128 blocks x 256 threads, 8 consecutive tokens/thread (int4 x2).
// Within-expert ordering is arbitrary; only grouping matters.
__global__ void k_scatter(const int* __restrict__ sel) {
    __shared__ int cnt[N_EXP];
    __shared__ int basesh[N_EXP];
    int tid = threadIdx.x;
    int lid = tid & 31;
    if (tid < N_EXP) cnt[tid] = 0;
    __syncthreads();

    int tgl = blockIdx.x * NTHREADS + tid;
    int m0 = tgl * 8;
    const int4* s4 = (const int4*)sel;
    int4 a = s4[tgl * 2];
    int4 b = s4[tgl * 2 + 1];
    int ev[8] = {a.x, a.y, a.z, a.w, b.x, b.y, b.z, b.w};
    int rv[8];

    unsigned lt = (1u << lid) - 1u;
#pragma unroll
    for (int i = 0; i < 8; i++) {
        int e = ev[i];
        unsigned msk = __match_any_sync(0xffffffffu, e);
        int leader = __ffs(msk) - 1;
        int pre = __popc(msk & lt);
        int wb = 0;
        if (lid == leader) wb = atomicAdd(&cnt[e], __popc(msk));
        wb = __shfl_sync(0xffffffffu, wb, leader);
        rv[i] = wb + pre;
    }
    __syncthreads();
    if (tid < N_EXP) basesh[tid] = atomicAdd(&g_cursor[tid], cnt[tid]);
    __syncthreads();
#pragma unroll
    for (int i = 0; i < 8; i++) {
        g_perm[basesh[ev[i]] + rv[i]] = m0 + i;
    }
}

__device__ __forceinline__ void mma_bf16(float* c, const uint32_t* a, const uint32_t* b) {
    asm volatile(
        "mma.sync.aligned.m16n8k16.row.col.f32.bf16.bf16.f32 "
        "{%0,%1,%2,%3}, {%4,%5,%6,%7}, {%8,%9}, {%0,%1,%2,%3};"
        : "+f"(c[0]), "+f"(c[1]), "+f"(c[2]), "+f"(c[3])
        : "r"(a[0]), "r"(a[1]), "r"(a[2]), "r"(a[3]), "r"(b[0]), "r"(b[1]));
}

// ---------------- K4: grouped GEMM via mma.sync (3x bf16 split) ----------------
// Block = 256 threads = 8 warps; tile = 128 tokens x 64 cols, K=64.
// Warp grid 4(M) x 2(N): warp computes 32x32 output.
__global__ void __launch_bounds__(NTHREADS) k_gemm_mma(
    const float* __restrict__ x, float* __restrict__ out)
{
    int t = blockIdx.x;
    if (t >= g_ntiles) return;
    int e    = g_tile_e[t];
    int base = g_tile_base[t];
    int rows = g_tile_rows[t];

    extern __shared__ unsigned short sh[];
    unsigned short* Ah = sh;
    unsigned short* Al = Ah + A_ELEMS;
    unsigned short* Bh = Al + A_ELEMS;
    unsigned short* Bl = Bh + B_ELEMS;

    int tid = threadIdx.x;
    int wid = tid >> 5;
    int lane = tid & 31;

    // ---- B: straight copy of prepped weights (hi+lo contiguous, 18432 B) ----
    {
        const uint4* src = (const uint4*)&g_wb[e][0][0];
        uint4* dst = (uint4*)Bh;
#pragma unroll
        for (int i = 0; i < 1152 / NTHREADS * NTHREADS; i += NTHREADS)
            dst[i + tid] = src[i + tid];
        if (tid < 1152 - (1152 / NTHREADS) * NTHREADS)
            dst[(1152 / NTHREADS) * NTHREADS + tid] =
                src[(1152 / NTHREADS) * NTHREADS + tid];
    }

    // ---- A: gather x rows, split hi/lo ----
    {
        int r    = tid >> 1;           // 0..127
        int half = tid & 1;            // k-range [half*32, half*32+32)
        bool valid = r < rows;
        const float4* xr = nullptr;
        if (valid) xr = (const float4*)x + (size_t)g_perm[base + r] * 16 + half * 8;
        unsigned short* ah = Ah + r * APITCH + half * 32;
        unsigned short* al = Al + r * APITCH + half * 32;
#pragma unroll
        for (int i = 0; i < 8; i++) {
            float4 v = valid ? xr[i] : make_float4(0.f, 0.f, 0.f, 0.f);
            unsigned short h0, l0, h1, l1, h2, l2, h3, l3;
            f2bf_split(v.x, h0, l0);
            f2bf_split(v.y, h1, l1);
            f2bf_split(v.z, h2, l2);
            f2bf_split(v.w, h3, l3);
            ((uint32_t*)(ah + i * 4))[0] = (uint32_t)h0 | ((uint32_t)h1 << 16);
            ((uint32_t*)(ah + i * 4))[1] = (uint32_t)h2 | ((uint32_t)h3 << 16);
            ((uint32_t*)(al + i * 4))[0] = (uint32_t)l0 | ((uint32_t)l1 << 16);
            ((uint32_t*)(al + i * 4))[1] = (uint32_t)l2 | ((uint32_t)l3 << 16);
        }
    }
    __syncthreads();

    // ---- mma mainloop ----
    int wm = wid & 3;                  // rows [wm*32, +32)
    int wn = wid >> 2;                 // cols [wn*32, +32)
    int lq = lane >> 2;                // 0..7
    int lr = lane & 3;                 // 0..3

    float acc[2][4][4];
#pragma unroll
    for (int mt = 0; mt < 2; mt++)
#pragma unroll
        for (int nt = 0; nt < 4; nt++)
#pragma unroll
            for (int i = 0; i < 4; i++) acc[mt][nt][i] = 0.f;

#pragma unroll
    for (int pass = 0; pass < 3; pass++) {
        const unsigned short* As = (pass == 2) ? Al : Ah;
        const unsigned short* Bs = (pass == 1) ? Bl : Bh;
#pragma unroll
        for (int kt = 0; kt < 4; kt++) {
            int c0 = kt * 16 + 2 * lr;
            uint32_t afrag[2][4];
#pragma unroll
            for (int mt = 0; mt < 2; mt++) {
                int r = wm * 32 + mt * 16 + lq;
                afrag[mt][0] = *(const uint32_t*)&As[r * APITCH + c0];
                afrag[mt][1] = *(const uint32_t*)&As[(r + 8) * APITCH + c0];
                afrag[mt][2] = *(const uint32_t*)&As[r * APITCH + c0 + 8];
                afrag[mt][3] = *(const uint32_t*)&As[(r + 8) * APITCH + c0 + 8];
            }
#pragma unroll
            for (int nt = 0; nt < 4; nt++) {
                int n = wn * 32 + nt * 8 + lq;
                uint32_t bfrag[2];
                bfrag[0] = *(const uint32_t*)&Bs[n * APITCH + c0];
                bfrag[1] = *(const uint32_t*)&Bs[n * APITCH + c0 + 8];
                mma_bf16(acc[0][nt], afrag[0], bfrag);
                mma_bf16(acc[1][nt], afrag[1], bfrag);
            }
        }
    }

    // ---- epilogue: scatter to out ----
#pragma unroll
    for (int mt = 0; mt < 2; mt++) {
#pragma unroll
        for (int half = 0; half < 2; half++) {
            int r = wm * 32 + mt * 16 + half * 8 + lq;
            if (r < rows) {
                int tok = g_perm[base + r];
                float* orow = out + (size_t)tok * 64 + wn * 32 + 2 * lr;
#pragma unroll
                for (int nt = 0; nt < 4; nt++) {
                    float2 v = make_float2(acc[mt][nt][half * 2],
                                           acc[mt][nt][half * 2 + 1]);
                    *(float2*)(orow + nt * 8) = v;
                }
            }
        }
    }
}

// ---------------- launch ----------------
extern "C" void kernel_launch(void* const* d_in, const int* in_sizes, int n_in,
                              void* d_out, int out_size) {
    const float* x   = (const float*)d_in[0];
    const int*   sel = (const int*)d_in[1];
    const float* w   = (const float*)d_in[2];
    float*       out = (float*)d_out;

    (void)in_sizes; (void)n_in; (void)out_size;

    cudaFuncSetAttribute(k_gemm_mma, cudaFuncAttributeMaxDynamicSharedMemorySize,
                         SMEM_BYTES);

    k_zero<<<1, 32>>>();
    k_wprep<<<N_EXP, NTHREADS>>>(w);
    k_hist<<<128, NTHREADS>>>(sel);
    k_scan<<<1, 32>>>();
    k_scatter<<<128, NTHREADS>>>(sel);
    k_gemm_mma<<<MAX_TILES, NTHREADS, SMEM_BYTES>>>(x, out);
}

// round 5
// speedup vs baseline: 1.3211x; 1.1249x over previous
#include <cuda_runtime.h>
#include <cuda_bf16.h>
#include <stdint.h>

// Problem constants
#define M_TOK   262144
#define K_DIM   64
#define N_DIM   64
#define N_EXP   8

#define TILE_M  128
#define NTHREADS 256
#define MAX_TILES (M_TOK / TILE_M + N_EXP)   // 2056

// smem layout (ushort units), pitch 72 bf16 per row (144B)
#define APITCH 72
#define A_ELEMS (128 * APITCH)          // 9216 ushort
#define B_ELEMS (64 * APITCH)           // 4608 ushort
// [Ah | Al | Bh | Bl]
#define SMEM_USHORTS (2 * A_ELEMS + 2 * B_ELEMS)
#define SMEM_BYTES (SMEM_USHORTS * 2)   // 55296

// ---------------- device scratch ----------------
__device__ int g_counts[N_EXP];
__device__ int g_cursor[N_EXP];
__device__ int g_perm[M_TOK];
__device__ int g_off[N_EXP + 1];    // token offsets per expert
__device__ int g_toff[N_EXP + 1];   // tile offsets per expert
__device__ int g_ntiles;
// prepped weights: per expert, [hi: 64n x 72k][lo: 64n x 72k] ushort (bf16)
__device__ unsigned short g_wb[N_EXP][2][64 * APITCH];

// ---------------- helpers ----------------
__device__ __forceinline__ void f2bf_split(float f, unsigned short& h, unsigned short& l) {
    __nv_bfloat16 hb = __float2bfloat16(f);
    __nv_bfloat16 lb = __float2bfloat16(f - __bfloat162float(hb));
    h = __bfloat16_as_ushort(hb);
    l = __bfloat16_as_ushort(lb);
}

__device__ __forceinline__ uint32_t smem_u32(const void* p) {
    uint32_t a;
    asm("{ .reg .u64 t; cvta.to.shared.u64 t, %1; cvt.u32.u64 %0, t; }"
        : "=r"(a) : "l"(p));
    return a;
}

__device__ __forceinline__ void ldsm_x4(uint32_t& r0, uint32_t& r1,
                                        uint32_t& r2, uint32_t& r3,
                                        uint32_t addr) {
    asm volatile("ldmatrix.sync.aligned.m8n8.x4.shared.b16 {%0,%1,%2,%3}, [%4];"
                 : "=r"(r0), "=r"(r1), "=r"(r2), "=r"(r3) : "r"(addr));
}

__device__ __forceinline__ void mma_bf16(float* c, const uint32_t* a, const uint32_t* b) {
    asm volatile(
        "mma.sync.aligned.m16n8k16.row.col.f32.bf16.bf16.f32 "
        "{%0,%1,%2,%3}, {%4,%5,%6,%7}, {%8,%9}, {%0,%1,%2,%3};"
        : "+f"(c[0]), "+f"(c[1]), "+f"(c[2]), "+f"(c[3])
        : "r"(a[0]), "r"(a[1]), "r"(a[2]), "r"(a[3]), "r"(b[0]), "r"(b[1]));
}

// ---------------- K_wprep: convert+transpose w (also zeroes counters) --------
__global__ void k_wprep(const float* __restrict__ w) {
    int e = blockIdx.x;
    int tid = threadIdx.x;
    if (e == 0 && tid < N_EXP) g_counts[tid] = 0;
    int n  = tid & 63;
    int kh = tid >> 6;                   // k range [kh*16, kh*16+16)
    const float* we = w + (size_t)e * (K_DIM * N_DIM);
    unsigned short* dh = &g_wb[e][0][n * APITCH];
    unsigned short* dl = &g_wb[e][1][n * APITCH];
#pragma unroll
    for (int i = 0; i < 8; i++) {
        int k = kh * 16 + 2 * i;
        float f0 = we[(size_t)k * N_DIM + n];
        float f1 = we[(size_t)(k + 1) * N_DIM + n];
        unsigned short h0, l0, h1, l1;
        f2bf_split(f0, h0, l0);
        f2bf_split(f1, h1, l1);
        *(uint32_t*)(dh + k) = (uint32_t)h0 | ((uint32_t)h1 << 16);
        *(uint32_t*)(dl + k) = (uint32_t)l0 | ((uint32_t)l1 << 16);
    }
}

// ---------------- K1: histogram (packed register counters) ----------------
__global__ void k_hist(const int* __restrict__ sel) {
    __shared__ int cnt[N_EXP];
    int tid = threadIdx.x;
    int lid = tid & 31;
    if (tid < N_EXP) cnt[tid] = 0;
    __syncthreads();

    int tgl = blockIdx.x * NTHREADS + tid;
    const int4* s4 = (const int4*)sel;
    int4 a = s4[tgl * 2];
    int4 b = s4[tgl * 2 + 1];

    unsigned long long pk0 = 0, pk1 = 0;
    int ev[8] = {a.x, a.y, a.z, a.w, b.x, b.y, b.z, b.w};
#pragma unroll
    for (int i = 0; i < 8; i++) {
        int e = ev[i];
        if (e < 4) pk0 += 1ull << (16 * e);
        else       pk1 += 1ull << (16 * (e - 4));
    }
#pragma unroll
    for (int o = 16; o > 0; o >>= 1) {
        pk0 += __shfl_down_sync(0xffffffffu, pk0, o);
        pk1 += __shfl_down_sync(0xffffffffu, pk1, o);
    }
    if (lid == 0) {
#pragma unroll
        for (int e = 0; e < 4; e++) {
            int c0 = (int)((pk0 >> (16 * e)) & 0xffff);
            int c1 = (int)((pk1 >> (16 * e)) & 0xffff);
            if (c0) atomicAdd(&cnt[e], c0);
            if (c1) atomicAdd(&cnt[e + 4], c1);
        }
    }
    __syncthreads();
    if (tid < N_EXP && cnt[tid]) atomicAdd(&g_counts[tid], cnt[tid]);
}

// ---------------- K2: tiny scan (1 thread) ----------------
__global__ void k_scan() {
    if (threadIdx.x == 0) {
        int o = 0, t = 0;
        for (int e = 0; e < N_EXP; e++) {
            int c = g_counts[e];
            g_off[e] = o;
            g_toff[e] = t;
            g_cursor[e] = o;
            o += c;
            t += (c + TILE_M - 1) >> 7;
        }
        g_off[N_EXP] = o;
        g_toff[N_EXP] = t;
        g_ntiles = t;
    }
}

// ---------------- K3: scatter (match_any ranking) ----------------
__global__ void k_scatter(const int* __restrict__ sel) {
    __shared__ int cnt[N_EXP];
    __shared__ int basesh[N_EXP];
    int tid = threadIdx.x;
    int lid = tid & 31;
    if (tid < N_EXP) cnt[tid] = 0;
    __syncthreads();

    int tgl = blockIdx.x * NTHREADS + tid;
    int m0 = tgl * 8;
    const int4* s4 = (const int4*)sel;
    int4 a = s4[tgl * 2];
    int4 b = s4[tgl * 2 + 1];
    int ev[8] = {a.x, a.y, a.z, a.w, b.x, b.y, b.z, b.w};
    int rv[8];

    unsigned lt = (1u << lid) - 1u;
#pragma unroll
    for (int i = 0; i < 8; i++) {
        int e = ev[i];
        unsigned msk = __match_any_sync(0xffffffffu, e);
        int leader = __ffs(msk) - 1;
        int pre = __popc(msk & lt);
        int wb = 0;
        if (lid == leader) wb = atomicAdd(&cnt[e], __popc(msk));
        wb = __shfl_sync(0xffffffffu, wb, leader);
        rv[i] = wb + pre;
    }
    __syncthreads();
    if (tid < N_EXP) basesh[tid] = atomicAdd(&g_cursor[tid], cnt[tid]);
    __syncthreads();
#pragma unroll
    for (int i = 0; i < 8; i++) {
        g_perm[basesh[ev[i]] + rv[i]] = m0 + i;
    }
}

// ---------------- K4: grouped GEMM via mma.sync + ldmatrix ----------------
__global__ void __launch_bounds__(NTHREADS) k_gemm_mma(
    const float* __restrict__ x, float* __restrict__ out)
{
    int t = blockIdx.x;
    if (t >= g_ntiles) return;
    // derive (e, base, rows) from offsets
    int e = 0;
#pragma unroll
    for (int ee = 1; ee < N_EXP; ee++)
        if (g_toff[ee] <= t) e = ee;
    int base = g_off[e] + (t - g_toff[e]) * TILE_M;
    int lim  = g_off[e + 1];
    int rows = lim - base;
    if (rows > TILE_M) rows = TILE_M;

    extern __shared__ unsigned short sh[];
    unsigned short* Ah = sh;
    unsigned short* Al = Ah + A_ELEMS;
    unsigned short* Bh = Al + A_ELEMS;
    unsigned short* Bl = Bh + B_ELEMS;

    int tid = threadIdx.x;
    int wid = tid >> 5;
    int lane = tid & 31;

    // ---- B: straight copy of prepped weights (hi+lo contiguous, 18432 B) ----
    {
        const uint4* src = (const uint4*)&g_wb[e][0][0];
        uint4* dst = (uint4*)Bh;
#pragma unroll
        for (int i = 0; i < 1024; i += NTHREADS)
            dst[i + tid] = src[i + tid];
        if (tid < 1152 - 1024)
            dst[1024 + tid] = src[1024 + tid];
    }

    // ---- A: gather x rows, split hi/lo ----
    {
        int r    = tid >> 1;           // 0..127
        int half = tid & 1;            // k-range [half*32, half*32+32)
        bool valid = r < rows;
        const float4* xr = nullptr;
        if (valid) xr = (const float4*)x + (size_t)g_perm[base + r] * 16 + half * 8;
        unsigned short* ah = Ah + r * APITCH + half * 32;
        unsigned short* al = Al + r * APITCH + half * 32;
#pragma unroll
        for (int i = 0; i < 8; i++) {
            float4 v = valid ? xr[i] : make_float4(0.f, 0.f, 0.f, 0.f);
            unsigned short h0, l0, h1, l1, h2, l2, h3, l3;
            f2bf_split(v.x, h0, l0);
            f2bf_split(v.y, h1, l1);
            f2bf_split(v.z, h2, l2);
            f2bf_split(v.w, h3, l3);
            ((uint32_t*)(ah + i * 4))[0] = (uint32_t)h0 | ((uint32_t)h1 << 16);
            ((uint32_t*)(ah + i * 4))[1] = (uint32_t)h2 | ((uint32_t)h3 << 16);
            ((uint32_t*)(al + i * 4))[0] = (uint32_t)l0 | ((uint32_t)l1 << 16);
            ((uint32_t*)(al + i * 4))[1] = (uint32_t)l2 | ((uint32_t)l3 << 16);
        }
    }
    __syncthreads();

    // ---- mma mainloop ----
    int wm = wid & 3;                  // rows [wm*32, +32)
    int wn = wid >> 2;                 // cols [wn*32, +32)
    int lq = lane >> 2;                // 0..7
    int lr = lane & 3;                 // 0..3

    // ldmatrix lane-address components: row = (lane&15), col8 = (lane&16)?8:0
    int lrow = lane & 15;
    int lcol = (lane & 16) ? 8 : 0;

    // A addresses (bytes): &A[(wm*32 + mt*16 + lrow)*APITCH + lcol]
    uint32_t aA0 = smem_u32(&Ah[(wm * 32 + lrow) * APITCH + lcol]);
    uint32_t aA1 = aA0 + 16 * APITCH * 2;
    // B addresses: &B[(wn*32 + ntg*16 + lrow)*APITCH + lcol]
    uint32_t aB0 = smem_u32(&Bh[(wn * 32 + lrow) * APITCH + lcol]);
    uint32_t aB1 = aB0 + 16 * APITCH * 2;

    const uint32_t A_LO = A_ELEMS * 2;   // byte offset Ah->Al
    const uint32_t B_LO = B_ELEMS * 2;   // byte offset Bh->Bl

    float acc[2][4][4];
#pragma unroll
    for (int mt = 0; mt < 2; mt++)
#pragma unroll
        for (int nt = 0; nt < 4; nt++)
#pragma unroll
            for (int i = 0; i < 4; i++) acc[mt][nt][i] = 0.f;

#pragma unroll
    for (int pass = 0; pass < 3; pass++) {
        uint32_t aoff = (pass == 2) ? A_LO : 0u;
        uint32_t boff = (pass == 1) ? B_LO : 0u;
#pragma unroll
        for (int kt = 0; kt < 4; kt++) {
            uint32_t koff = (uint32_t)(kt * 16 * 2);
            uint32_t af0[4], af1[4];
            ldsm_x4(af0[0], af0[1], af0[2], af0[3], aA0 + aoff + koff);
            ldsm_x4(af1[0], af1[1], af1[2], af1[3], aA1 + aoff + koff);
            // B: two x4 loads cover nt=0..3.
            // regs: r0 = b0 (n group lo 8), r1 = b0 (n group hi 8),
            //       r2 = b1 (lo), r3 = b1 (hi)
            uint32_t bf01[4], bf23[4];
            ldsm_x4(bf01[0], bf01[1], bf01[2], bf01[3], aB0 + boff + koff);
            ldsm_x4(bf23[0], bf23[1], bf23[2], bf23[3], aB1 + boff + koff);
            uint32_t bb[4][2] = {
                {bf01[0], bf01[2]}, {bf01[1], bf01[3]},
                {bf23[0], bf23[2]}, {bf23[1], bf23[3]}
            };
#pragma unroll
            for (int nt = 0; nt < 4; nt++) {
                mma_bf16(acc[0][nt], af0, bb[nt]);
                mma_bf16(acc[1][nt], af1, bb[nt]);
            }
        }
    }

    // ---- epilogue: scatter to out ----
#pragma unroll
    for (int mt = 0; mt < 2; mt++) {
#pragma unroll
        for (int half = 0; half < 2; half++) {
            int r = wm * 32 + mt * 16 + half * 8 + lq;
            if (r < rows) {
                int tok = g_perm[base + r];
                float* orow = out + (size_t)tok * 64 + wn * 32 + 2 * lr;
#pragma unroll
                for (int nt = 0; nt < 4; nt++) {
                    float2 v = make_float2(acc[mt][nt][half * 2],
                                           acc[mt][nt][half * 2 + 1]);
                    *(float2*)(orow + nt * 8) = v;
                }
            }
        }
    }
}

// ---------------- launch ----------------
extern "C" void kernel_launch(void* const* d_in, const int* in_sizes, int n_in,
                              void* d_out, int out_size) {
    const float* x   = (const float*)d_in[0];
    const int*   sel = (const int*)d_in[1];
    const float* w   = (const float*)d_in[2];
    float*       out = (float*)d_out;

    (void)in_sizes; (void)n_in; (void)out_size;

    cudaFuncSetAttribute(k_gemm_mma, cudaFuncAttributeMaxDynamicSharedMemorySize,
                         SMEM_BYTES);

    k_wprep<<<N_EXP, NTHREADS>>>(w);
    k_hist<<<128, NTHREADS>>>(sel);
    k_scan<<<1, 32>>>();
    k_scatter<<<128, NTHREADS>>>(sel);
    k_gemm_mma<<<MAX_TILES, NTHREADS, SMEM_BYTES>>>(x, out);
}

// round 8
// speedup vs baseline: 1.5982x; 1.2097x over previous
#include <cuda_runtime.h>
#include <cuda_fp16.h>
#include <stdint.h>

// Problem constants
#define M_TOK   262144
#define K_DIM   64
#define N_DIM   64
#define N_EXP   8

#define TILE_M  128
#define NTHREADS 256
#define MAX_TILES (M_TOK / TILE_M + N_EXP)   // 2056

// smem byte layout: Ah[128x64 fp16, SW128] | Al | Bh[64x64 fp16, SW128]
#define OFF_AH 0
#define OFF_AL 16384
#define OFF_BH 32768
#define SMEM_BYTES 40960

#define SW(b) ((b) ^ (((b) >> 3) & 0x70))

// ---------------- device scratch ----------------
__device__ int g_counts[N_EXP];
__device__ int g_cursor[N_EXP];
__device__ int g_perm[M_TOK];
__device__ int g_off[N_EXP + 1];
__device__ int g_toff[N_EXP + 1];
__device__ int g_ntiles;
// prepped weights: per expert, fp16 [64n][64k] with SW128 swizzle (8KB)
__device__ unsigned short g_wh[N_EXP][64 * 64];

// ---------------- helpers ----------------
__device__ __forceinline__ uint32_t pack2h(__half a, __half b) {
    return (uint32_t)__half_as_ushort(a) | ((uint32_t)__half_as_ushort(b) << 16);
}

__device__ __forceinline__ uint32_t smem_u32(const void* p) {
    uint32_t a;
    asm("{ .reg .u64 t; cvta.to.shared.u64 t, %1; cvt.u32.u64 %0, t; }"
        : "=r"(a) : "l"(p));
    return a;
}

__device__ __forceinline__ void ldsm_x4(uint32_t& r0, uint32_t& r1,
                                        uint32_t& r2, uint32_t& r3,
                                        uint32_t addr) {
    asm volatile("ldmatrix.sync.aligned.m8n8.x4.shared.b16 {%0,%1,%2,%3}, [%4];"
                 : "=r"(r0), "=r"(r1), "=r"(r2), "=r"(r3) : "r"(addr));
}

__device__ __forceinline__ void mma_f16(float* c, const uint32_t* a, const uint32_t* b) {
    asm volatile(
        "mma.sync.aligned.m16n8k16.row.col.f32.f16.f16.f32 "
        "{%0,%1,%2,%3}, {%4,%5,%6,%7}, {%8,%9}, {%0,%1,%2,%3};"
        : "+f"(c[0]), "+f"(c[1]), "+f"(c[2]), "+f"(c[3])
        : "r"(a[0]), "r"(a[1]), "r"(a[2]), "r"(a[3]), "r"(b[0]), "r"(b[1]));
}

// ---------------- K_wprep: w -> fp16, transposed [n][k], SW128 (+zero cnts) --
__global__ void k_wprep(const float* __restrict__ w) {
    int e = blockIdx.x;
    int tid = threadIdx.x;
    if (e == 0 && tid < N_EXP) g_counts[tid] = 0;
    int n  = tid & 63;
    int kh = tid >> 6;                   // k range [kh*16, +16)
    const float* we = w + (size_t)e * (K_DIM * N_DIM);
    char* dst = (char*)g_wh[e];
#pragma unroll
    for (int i = 0; i < 8; i++) {
        int k = kh * 16 + 2 * i;
        __half h0 = __float2half(we[(size_t)k * N_DIM + n]);
        __half h1 = __float2half(we[(size_t)(k + 1) * N_DIM + n]);
        uint32_t b = (uint32_t)n * 128u + (uint32_t)k * 2u;
        *(uint32_t*)(dst + SW(b)) = pack2h(h0, h1);
    }
}

// ---------------- K1: histogram (256 blocks, 4 tokens/thread) ----------------
__global__ void k_hist(const int* __restrict__ sel) {
    __shared__ int cnt[N_EXP];
    int tid = threadIdx.x;
    int lid = tid & 31;
    if (tid < N_EXP) cnt[tid] = 0;
    __syncthreads();

    int tgl = blockIdx.x * NTHREADS + tid;
    int4 a = ((const int4*)sel)[tgl];

    unsigned long long pk0 = 0, pk1 = 0;
    int ev[4] = {a.x, a.y, a.z, a.w};
#pragma unroll
    for (int i = 0; i < 4; i++) {
        int e = ev[i];
        if (e < 4) pk0 += 1ull << (16 * e);
        else       pk1 += 1ull << (16 * (e - 4));
    }
#pragma unroll
    for (int o = 16; o > 0; o >>= 1) {
        pk0 += __shfl_down_sync(0xffffffffu, pk0, o);
        pk1 += __shfl_down_sync(0xffffffffu, pk1, o);
    }
    if (lid == 0) {
#pragma unroll
        for (int e = 0; e < 4; e++) {
            int c0 = (int)((pk0 >> (16 * e)) & 0xffff);
            int c1 = (int)((pk1 >> (16 * e)) & 0xffff);
            if (c0) atomicAdd(&cnt[e], c0);
            if (c1) atomicAdd(&cnt[e + 4], c1);
        }
    }
    __syncthreads();
    if (tid < N_EXP && cnt[tid]) atomicAdd(&g_counts[tid], cnt[tid]);
}

// ---------------- K2: tiny scan (1 thread) ----------------
__global__ void k_scan() {
    if (threadIdx.x == 0) {
        int o = 0, t = 0;
        for (int e = 0; e < N_EXP; e++) {
            int c = g_counts[e];
            g_off[e] = o;
            g_toff[e] = t;
            g_cursor[e] = o;
            o += c;
            t += (c + TILE_M - 1) >> 7;
        }
        g_off[N_EXP] = o;
        g_toff[N_EXP] = t;
        g_ntiles = t;
    }
}

// ---------------- K3: scatter (256 blocks, 4 tokens/thread) ----------------
__global__ void k_scatter(const int* __restrict__ sel) {
    __shared__ int cnt[N_EXP];
    __shared__ int basesh[N_EXP];
    int tid = threadIdx.x;
    int lid = tid & 31;
    if (tid < N_EXP) cnt[tid] = 0;
    __syncthreads();

    int tgl = blockIdx.x * NTHREADS + tid;
    int m0 = tgl * 4;
    int4 a = ((const int4*)sel)[tgl];
    int ev[4] = {a.x, a.y, a.z, a.w};
    int rv[4];

    unsigned lt = (1u << lid) - 1u;
#pragma unroll
    for (int i = 0; i < 4; i++) {
        int e = ev[i];
        unsigned msk = __match_any_sync(0xffffffffu, e);
        int leader = __ffs(msk) - 1;
        int pre = __popc(msk & lt);
        int wb = 0;
        if (lid == leader) wb = atomicAdd(&cnt[e], __popc(msk));
        wb = __shfl_sync(0xffffffffu, wb, leader);
        rv[i] = wb + pre;
    }
    __syncthreads();
    if (tid < N_EXP) basesh[tid] = atomicAdd(&g_cursor[tid], cnt[tid]);
    __syncthreads();
#pragma unroll
    for (int i = 0; i < 4; i++) {
        g_perm[basesh[ev[i]] + rv[i]] = m0 + i;
    }
}

// ---------------- K4: grouped GEMM, 2-pass fp16 split ----------------
// D = Ah@Bh + Al@Bh = X @ fp16(W_e), fp32 accumulate.
// Block = 256 thr = 8 warps; warp grid 4(M) x 2(N), warp tile 32x32.
__global__ void __launch_bounds__(NTHREADS) k_gemm_mma(
    const float* __restrict__ x, float* __restrict__ out)
{
    int t = blockIdx.x;
    if (t >= g_ntiles) return;
    int e = 0;
#pragma unroll
    for (int ee = 1; ee < N_EXP; ee++)
        if (g_toff[ee] <= t) e = ee;
    int base = g_off[e] + (t - g_toff[e]) * TILE_M;
    int lim  = g_off[e + 1];
    int rows = lim - base;
    if (rows > TILE_M) rows = TILE_M;

    extern __shared__ char sm[];
    int tid = threadIdx.x;
    int wid = tid >> 5;
    int lane = tid & 31;

    // ---- B: copy prepped fp16 weights (8192B, SW128 already applied) ----
    {
        const uint4* src = (const uint4*)&g_wh[e][0];
        uint4* dst = (uint4*)(sm + OFF_BH);
        dst[tid]       = src[tid];
        dst[tid + 256] = src[tid + 256];
    }

    // ---- A: gather x rows, split fp16 hi/lo, swizzled stores ----
    {
        int r    = tid >> 1;           // 0..127
        int half = tid & 1;            // k range [half*32, +32)
        bool valid = r < rows;
        const float4* xr = nullptr;
        if (valid) xr = (const float4*)x + (size_t)g_perm[base + r] * 16 + half * 8;
        uint32_t rb = (uint32_t)r * 128u + (uint32_t)half * 64u;
#pragma unroll
        for (int i = 0; i < 8; i++) {
            float4 v = valid ? xr[i] : make_float4(0.f, 0.f, 0.f, 0.f);
            __half hx = __float2half(v.x), hy = __float2half(v.y);
            __half hz = __float2half(v.z), hw = __float2half(v.w);
            __half lx = __float2half(v.x - __half2float(hx));
            __half ly = __float2half(v.y - __half2float(hy));
            __half lz = __float2half(v.z - __half2float(hz));
            __half lw = __float2half(v.w - __half2float(hw));
            uint32_t sb = SW(rb + (uint32_t)i * 8u);
            *(uint2*)(sm + OFF_AH + sb) = make_uint2(pack2h(hx, hy), pack2h(hz, hw));
            *(uint2*)(sm + OFF_AL + sb) = make_uint2(pack2h(lx, ly), pack2h(lz, lw));
        }
    }
    __syncthreads();

    // ---- mainloop ----
    int wm = wid & 3;                  // rows [wm*32, +32)
    int wn = wid >> 2;                 // cols [wn*32, +32)
    int lq = lane >> 2;                // 0..7
    int lr = lane & 3;                 // 0..3

    int lrow = lane & 15;
    uint32_t lcol16 = (lane & 16) ? 16u : 0u;
    uint32_t sbase = smem_u32(sm);

    // Swizzle decomposition: SW(rowbyte + colbyte) = rowbyte + (colbyte ^ m),
    // m = (rowbyte>>3)&0x70 (row mod 8 only). +16 rows (+2048) and region
    // offsets (+16384) preserve row mod 8 -> same m.
    uint32_t rowA = (uint32_t)(wm * 32 + lrow) * 128u;
    uint32_t mA   = (rowA >> 3) & 0x70u;
    uint32_t aArow = sbase + OFF_AH + rowA;
    uint32_t rowB = (uint32_t)(wn * 32 + lrow) * 128u;
    uint32_t mB   = (rowB >> 3) & 0x70u;
    uint32_t aBrow = sbase + OFF_BH + rowB;

    float acc[2][4][4];
#pragma unroll
    for (int mt = 0; mt < 2; mt++)
#pragma unroll
        for (int nt = 0; nt < 4; nt++)
#pragma unroll
            for (int i = 0; i < 4; i++) acc[mt][nt][i] = 0.f;

#pragma unroll
    for (int kt = 0; kt < 4; kt++) {
        uint32_t ko = (uint32_t)kt * 32u;
        uint32_t colA = (lcol16 + ko) ^ mA;
        uint32_t colB = (lcol16 + ko) ^ mB;
        uint32_t bf01[4], bf23[4];
        ldsm_x4(bf01[0], bf01[1], bf01[2], bf01[3], aBrow + colB);
        ldsm_x4(bf23[0], bf23[1], bf23[2], bf23[3], aBrow + 2048u + colB);
        uint32_t bb[4][2] = {
            {bf01[0], bf01[2]}, {bf01[1], bf01[3]},
            {bf23[0], bf23[2]}, {bf23[1], bf23[3]}
        };
        uint32_t ah0[4], ah1[4], al0[4], al1[4];
        ldsm_x4(ah0[0], ah0[1], ah0[2], ah0[3], aArow + colA);
        ldsm_x4(ah1[0], ah1[1], ah1[2], ah1[3], aArow + 2048u + colA);
        ldsm_x4(al0[0], al0[1], al0[2], al0[3], aArow + 16384u + colA);
        ldsm_x4(al1[0], al1[1], al1[2], al1[3], aArow + 18432u + colA);
#pragma unroll
        for (int nt = 0; nt < 4; nt++) {
            mma_f16(acc[0][nt], ah0, bb[nt]);
            mma_f16(acc[1][nt], ah1, bb[nt]);
        }
#pragma unroll
        for (int nt = 0; nt < 4; nt++) {
            mma_f16(acc[0][nt], al0, bb[nt]);
            mma_f16(acc[1][nt], al1, bb[nt]);
        }
    }

    // ---- epilogue: scatter to out ----
#pragma unroll
    for (int mt = 0; mt < 2; mt++) {
#pragma unroll
        for (int half = 0; half < 2; half++) {
            int r = wm * 32 + mt * 16 + half * 8 + lq;
            if (r < rows) {
                int tok = g_perm[base + r];
                float* orow = out + (size_t)tok * 64 + wn * 32 + 2 * lr;
#pragma unroll
                for (int nt = 0; nt < 4; nt++) {
                    float2 v = make_float2(acc[mt][nt][half * 2],
                                           acc[mt][nt][half * 2 + 1]);
                    *(float2*)(orow + nt * 8) = v;
                }
            }
        }
    }
}

// ---------------- launch ----------------
extern "C" void kernel_launch(void* const* d_in, const int* in_sizes, int n_in,
                              void* d_out, int out_size) {
    const float* x   = (const float*)d_in[0];
    const int*   sel = (const int*)d_in[1];
    const float* w   = (const float*)d_in[2];
    float*       out = (float*)d_out;

    (void)in_sizes; (void)n_in; (void)out_size;

    cudaFuncSetAttribute(k_gemm_mma, cudaFuncAttributeMaxDynamicSharedMemorySize,
                         SMEM_BYTES);

    k_wprep<<<N_EXP, NTHREADS>>>(w);
    k_hist<<<256, NTHREADS>>>(sel);
    k_scan<<<1, 32>>>();
    k_scatter<<<256, NTHREADS>>>(sel);
    k_gemm_mma<<<MAX_TILES, NTHREADS, SMEM_BYTES>>>(x, out);
}